// round 17
// baseline (speedup 1.0000x reference)
#include <cuda_runtime.h>
#include <cuda_fp16.h>
#include <cstdint>
#include <math.h>

#define H 256
#define BM 32
#define NSEG 512
#define AS 528           // A row stride in bytes (264 fp16, padded)

typedef unsigned long long u64;
typedef unsigned int       u32;

// -------- device scratch (no allocations allowed) --------
__device__ int g_is64;
// W (fp16) packed per-lane for LDG.128 (16B/lane stride, warp = 512B):
// u32 offset = gemm*32768 + ks*2048 + w*256 + p*128 + lane*4 + jj*2 + reg
__device__ __align__(16) u32 g_Wb[65536];

// -------- SMEM layout (bytes) --------
#define OFF_AHI   0                    // [32][264] fp16 = 16896
// g tile (final): fp32 [32][264] = 33792 bytes overlays 0..33791
#define OFF_BSEG  33792                // 32 ints = 128
#define OFF_BIAS  33920                // b1[256], b2[256] fp32 = 2048
#define SMEM_TOTAL 35968

// -------- PTX helpers (legal on plain sm_103 target) --------
__device__ __forceinline__ void ldm4(u32* r, u32 addr) {
    asm volatile("ldmatrix.sync.aligned.m8n8.x4.shared.b16 {%0,%1,%2,%3},[%4];"
        : "=r"(r[0]), "=r"(r[1]), "=r"(r[2]), "=r"(r[3]) : "r"(addr));
}
__device__ __forceinline__ void mma16816(float* d, const u32* a, const u32* b) {
    asm volatile(
        "mma.sync.aligned.m16n8k16.row.col.f32.f16.f16.f32 "
        "{%0,%1,%2,%3},{%4,%5,%6,%7},{%8,%9},{%0,%1,%2,%3};"
        : "+f"(d[0]), "+f"(d[1]), "+f"(d[2]), "+f"(d[3])
        : "r"(a[0]), "r"(a[1]), "r"(a[2]), "r"(a[3]), "r"(b[0]), "r"(b[1]));
}

// ---------------------------------------------------------------------------
// Kernel 1: W prep (fp32 -> fp16, LDG.128 fragment layout) + zero out +
// batch dtype detection. 512 blocks x 256 threads.
// ---------------------------------------------------------------------------
__global__ void prep_kernel(const float* __restrict__ W1,
                            const float* __restrict__ W2,
                            float* out,
                            const void* batch, int N) {
    int id = blockIdx.x * 256 + threadIdx.x;     // 131072 total
    // zero output (262144 floats)
    out[id] = 0.0f;
    out[id + 131072] = 0.0f;
    if (id == 0) {
        const int* bw = (const int*)batch;
        int o = ((N - 1) & 1) ? (N - 1) : (N - 2);
        int orv = 0;
        if (o >= 4) orv = bw[o] | bw[o - 2] | bw[o - 4];
        else if (o >= 0) orv = bw[o];
        g_is64 = (orv == 0) ? 1 : 0;
    }
    // W pack: lane gets 16B/uint4 per (w, p) pair -> coalesced LDG.128
    int gemm = id >> 16, rem = id & 65535;
    int n = rem >> 8, k = rem & 255;
    float wv = (gemm ? W2 : W1)[n * H + k];
    __half hi = __float2half_rn(wv);
    int ks = k >> 4, kk = k & 15;
    int w  = n >> 5;           // owning warp
    int j  = (n >> 3) & 3;     // nt within warp (0..3)
    int p  = j >> 1, jj = j & 1;
    int lane = (n & 7) * 4 + ((kk & 7) >> 1);
    int reg  = kk >> 3;
    int half_i = kk & 1;
    u32 base = (u32)(gemm * 32768 + ks * 2048 + w * 256 + p * 128
                     + lane * 4 + jj * 2 + reg);
    __half* wb = (__half*)g_Wb;
    wb[(size_t)base * 2 + half_i] = hi;
}

// ---------------------------------------------------------------------------
// Kernel 2: fused  relu(xW1^T+b1) -> sigmoid(hW2^T+b2) gate -> segment reduce.
// Plain fp16 HMMA. BM=32, warp grid 1x8 (mt=2, nt=4), no B duplication,
// 4 CTAs/SM (8 warps/SMSP). B: 2 x LDG.128 per k-step (coalesced 512B/warp),
// double-buffered; step-0 preload overlaps the x tile load.
// ---------------------------------------------------------------------------
extern "C" __global__ void __launch_bounds__(256, 4)
fused_kernel(const float* __restrict__ x, const void* __restrict__ batch,
             const float* __restrict__ b1, const float* __restrict__ b2,
             float* __restrict__ out, int N)
{
    extern __shared__ char smem[];
    const u32 sb = (u32)__cvta_generic_to_shared(smem);
    const int tid  = threadIdx.x;
    const int w    = tid >> 5;          // warp 0..7: output cols w*32..w*32+31
    const int lane = tid & 31;
    const int row0 = blockIdx.x * BM;
    float* sb1 = (float*)(smem + OFF_BIAS);
    float* sb2 = sb1 + H;
    int* bseg = (int*)(smem + OFF_BSEG);

    // per-warp B base (u32 index); +2048 per k-step, +32768 per gemm
    const u32* bwp = g_Wb + (u32)(w * 256 + lane * 4);

    uint4 bh[2][2];
    // GEMM1 step-0 preload — overlaps the x global loads below
    bh[0][0] = __ldg((const uint4*)(bwp));
    bh[0][1] = __ldg((const uint4*)(bwp + 128));

    // ---- bias + segment ids ----
    sb1[tid] = b1[tid];
    sb2[tid] = b2[tid];
    if (tid < BM) {
        int r = row0 + tid;
        int s = -1;
        if (r < N) {
            if (g_is64) s = (int)((const long long*)batch)[r];
            else        s = ((const int*)batch)[r];
        }
        bseg[tid] = s;
    }

    // ---- load x tile fp32 -> fp16 into AHI ([32][264] padded) ----
    {
        const float4* xg = (const float4*)x;
        #pragma unroll
        for (int it = 0; it < 8; ++it) {
            int f = tid + it * 256;            // 2048 float4s
            int r = f >> 6, k4 = f & 63;
            float4 v = make_float4(0.f, 0.f, 0.f, 0.f);
            if (row0 + r < N) v = xg[(size_t)(row0 + r) * (H / 4) + k4];
            __half2 h01 = __floats2half2_rn(v.x, v.y);
            __half2 h23 = __floats2half2_rn(v.z, v.w);
            char* pa = smem + OFF_AHI + r * AS + k4 * 8;
            *(__half2*)pa = h01;  *(__half2*)(pa + 4) = h23;
        }
    }
    __syncthreads();   // x tile visible to all warps

    float acc[2][4][4];
    #pragma unroll
    for (int i = 0; i < 2; ++i)
        #pragma unroll
        for (int j = 0; j < 4; ++j)
            #pragma unroll
            for (int q = 0; q < 4; ++q) acc[i][j][q] = 0.f;

    // ---- 2 GEMMs, K=256 = 16 full k16-steps each ----
    #pragma unroll 1
    for (int g = 0; g < 2; ++g) {
        const u32* bp = bwp + g * 32768;   // this gemm's step-0 base

        if (g == 1) {                      // preload GEMM2 step 0
            bh[0][0] = __ldg((const uint4*)(bp));
            bh[0][1] = __ldg((const uint4*)(bp + 128));
        }

        // A smem address; advances 32 bytes per k-step
        u32 ap = sb + OFF_AHI + (lane & 15) * AS + ((lane >> 4) << 4);

        u32 ah[2][4];
        #pragma unroll 2
        for (int ks = 0; ks < 16; ++ks) {
            const int cur = ks & 1;
            ldm4(ah[0], ap);
            ldm4(ah[1], ap + 16 * AS);
            ap += 32;
            // prefetch next step's B fragments (2 x LDG.128)
            if (ks < 15) {
                const u32* pn = bp + 2048;
                bh[cur ^ 1][0] = __ldg((const uint4*)(pn));
                bh[cur ^ 1][1] = __ldg((const uint4*)(pn + 128));
            }
            bp += 2048;
            // 8 MMAs: 2 mt x 4 nt (nt j -> uint4 p=j>>1, pair (j&1)*2)
            #pragma unroll
            for (int mt = 0; mt < 2; ++mt)
                #pragma unroll
                for (int j = 0; j < 4; ++j)
                    mma16816(acc[mt][j], ah[mt],
                             ((const u32*)&bh[cur][j >> 1]) + (j & 1) * 2);
        }

        // ---- GEMM boundary: h = relu(D1+b1) -> fp16 back into A ----
        if (g == 0) {
            __syncthreads();   // all warps done READING x before overwrite
            #pragma unroll
            for (int mt = 0; mt < 2; ++mt)
                #pragma unroll
                for (int j = 0; j < 4; ++j) {
                    float* a4 = acc[mt][j];
                    int r  = mt * 16 + (lane >> 2);
                    int cc = w * 32 + j * 8 + (lane & 3) * 2;
                    float bx = sb1[cc], by = sb1[cc + 1];
                    float h0 = fmaxf(a4[0] + bx, 0.f), h1 = fmaxf(a4[1] + by, 0.f);
                    float h2 = fmaxf(a4[2] + bx, 0.f), h3 = fmaxf(a4[3] + by, 0.f);
                    __half2 hiA = __floats2half2_rn(h0, h1);
                    __half2 hiB = __floats2half2_rn(h2, h3);
                    *(__half2*)(smem + OFF_AHI + r * AS + cc * 2)       = hiA;
                    *(__half2*)(smem + OFF_AHI + (r + 8) * AS + cc * 2) = hiB;
                }
            __syncthreads();   // h visible to all warps before GEMM2
            #pragma unroll
            for (int i = 0; i < 2; ++i)
                #pragma unroll
                for (int j = 0; j < 4; ++j)
                    #pragma unroll
                    for (int q = 0; q < 4; ++q) acc[i][j][q] = 0.f;
        }
    }

    // ---- final epilogue: g = h * sigmoid(D2+b2); g overlays A region ----
    float* gt = (float*)smem;   // [32][264] fp32 over A region
    {
        float gv[2][4][4];
        #pragma unroll
        for (int mt = 0; mt < 2; ++mt)
            #pragma unroll
            for (int j = 0; j < 4; ++j) {
                float* a4 = acc[mt][j];
                int r  = mt * 16 + (lane >> 2);
                int cc = w * 32 + j * 8 + (lane & 3) * 2;
                float bx = sb2[cc], by = sb2[cc + 1];
                float2 hA = __half22float2(*(__half2*)(smem + OFF_AHI + r * AS + cc * 2));
                float2 hB = __half22float2(*(__half2*)(smem + OFF_AHI + (r + 8) * AS + cc * 2));
                gv[mt][j][0] = hA.x / (1.f + __expf(-(a4[0] + bx)));
                gv[mt][j][1] = hA.y / (1.f + __expf(-(a4[1] + by)));
                gv[mt][j][2] = hB.x / (1.f + __expf(-(a4[2] + bx)));
                gv[mt][j][3] = hB.y / (1.f + __expf(-(a4[3] + by)));
            }
        __syncthreads();   // everyone done reading h before overwrite
        #pragma unroll
        for (int mt = 0; mt < 2; ++mt)
            #pragma unroll
            for (int j = 0; j < 4; ++j) {
                int r  = mt * 16 + (lane >> 2);
                int cc = w * 32 + j * 8 + (lane & 3) * 2;
                *(float2*)&gt[r * 264 + cc]       = make_float2(gv[mt][j][0], gv[mt][j][1]);
                *(float2*)&gt[(r + 8) * 264 + cc] = make_float2(gv[mt][j][2], gv[mt][j][3]);
            }
    }
    __syncthreads();

    // ---- segment reduction: sorted batch -> runs; one thread per column ----
    {
        const int ccol = tid;              // 256 threads = 256 columns
        int cur = bseg[0];
        float rsum = 0.f, rmax = 0.f;
        #pragma unroll 1
        for (int r = 0; r < BM; ++r) {
            int s = bseg[r];
            float g = gt[r * 264 + ccol];
            if (s != cur) {
                if (cur >= 0) {
                    atomicAdd(&out[(size_t)cur * 2 * H + H + ccol], rsum);
                    atomicMax((unsigned int*)&out[(size_t)cur * 2 * H + ccol],
                              __float_as_uint(rmax));   // g >= 0 always
                }
                cur = s; rsum = 0.f; rmax = 0.f;
            }
            if (s >= 0) { rsum += g; rmax = fmaxf(rmax, g); }
        }
        if (cur >= 0) {
            atomicAdd(&out[(size_t)cur * 2 * H + H + ccol], rsum);
            atomicMax((unsigned int*)&out[(size_t)cur * 2 * H + ccol],
                      __float_as_uint(rmax));
        }
    }
}

// ---------------------------------------------------------------------------
// Kernel 3: mean = sum / count (count via binary search on sorted batch).
// ---------------------------------------------------------------------------
__global__ void finalize_kernel(float* out, const void* batch, int N) {
    __shared__ float inv;
    int seg = blockIdx.x;
    if (threadIdx.x == 0) {
        int lb, ub;
        if (g_is64) {
            const long long* b = (const long long*)batch;
            int lo = 0, hi = N;
            while (lo < hi) { int m = (lo + hi) >> 1; if (b[m] < (long long)seg) lo = m + 1; else hi = m; }
            lb = lo;
            lo = lb; hi = N;
            while (lo < hi) { int m = (lo + hi) >> 1; if (b[m] < (long long)(seg + 1)) lo = m + 1; else hi = m; }
            ub = lo;
        } else {
            const int* b = (const int*)batch;
            int lo = 0, hi = N;
            while (lo < hi) { int m = (lo + hi) >> 1; if (b[m] < seg) lo = m + 1; else hi = m; }
            lb = lo;
            lo = lb; hi = N;
            while (lo < hi) { int m = (lo + hi) >> 1; if (b[m] < seg + 1) lo = m + 1; else hi = m; }
            ub = lo;
        }
        int cnt = ub - lb;
        inv = cnt > 0 ? 1.0f / (float)cnt : 1.0f;
    }
    __syncthreads();
    out[(size_t)seg * 2 * H + H + threadIdx.x] *= inv;
}

extern "C" void kernel_launch(void* const* d_in, const int* in_sizes, int n_in,
                              void* d_out, int out_size) {
    const float* x     = (const float*)d_in[0];
    const void*  batch = d_in[1];
    const float* W1    = (const float*)d_in[2];
    const float* b1    = (const float*)d_in[3];
    const float* W2    = (const float*)d_in[4];
    const float* b2    = (const float*)d_in[5];
    float* out = (float*)d_out;

    int N = in_sizes[0] / H;

    cudaFuncSetAttribute(fused_kernel,
                         cudaFuncAttributeMaxDynamicSharedMemorySize, SMEM_TOTAL);

    prep_kernel<<<512, 256>>>(W1, W2, out, batch, N);

    int nblk = (N + BM - 1) / BM;
    fused_kernel<<<nblk, 256, SMEM_TOTAL>>>(x, batch, b1, b2, out, N);

    finalize_kernel<<<NSEG, 256>>>(out, batch, N);
}